// round 16
// baseline (speedup 1.0000x reference)
#include <cuda_runtime.h>
#include <cuda_bf16.h>
#include <math.h>

#define HID   256
#define ATTN  32
#define MAXU  10000
#define MAXI  30000
#define MAXE  500000
#define MAXN  40000
#define MPAD  40960          // 320 * 128, padded M for the GEMM
#define THR   0.8f

// ---------------- scratch (device globals: no allocations allowed) ----------
__device__ float         g_U1[MAXU * ATTN];
__device__ float         g_I1[MAXI * ATTN];
__device__ float         g_w[MAXE];
__device__ float         g_xw[(size_t)MAXN * HID];
__device__ float         g_deg[MAXN];
__device__ int           g_count;
__device__ unsigned      g_maxbits;
__device__ int           g_argidx;
// split-bf16 GEMM operands
__device__ __nv_bfloat16 g_Ahi[(size_t)MPAD * HID];
__device__ __nv_bfloat16 g_Alo[(size_t)MPAD * HID];
__device__ __nv_bfloat16 g_Bhi[HID * HID];   // W^T  [n][k]
__device__ __nv_bfloat16 g_Blo[HID * HID];   // W^T  [n][k]

// ---------------- K1: attention projections + fused setup + X bf16 export ----
// Setup jobs (deg init, counters, A-pad zero, W split-transpose) are spread
// over the first 65536 global threads; stream order publishes them to the
// consumers (edge_weight, GEMM).
#define ABM 128
#define ABK 32
#define XPAD 4               // row stride 36 floats = 144 B: 16B-aligned float4s

__global__ __launch_bounds__(256, 3)
void attn_precompute_kernel(const float* __restrict__ uemb,
                            const float* __restrict__ iemb,
                            const float* __restrict__ W1,
                            const float* __restrict__ gW,
                            int n_users, int n_items, int n_nodes, int ublk) {
    // ---- fused setup jobs ----
    int gt = blockIdx.x * blockDim.x + threadIdx.x;
    if (gt * 4 < n_nodes) {
        float4 one = make_float4(1.f, 1.f, 1.f, 1.f);
        *(float4*)&g_deg[gt * 4] = one;
    }
    if (gt == 0) { g_count = 0; g_maxbits = 0u; g_argidx = 0x7fffffff; }
    if (gt < (MPAD - MAXN) * (HID / 8)) {
        size_t off = (size_t)MAXN * HID + (size_t)gt * 8;
        uint4 z = make_uint4(0u, 0u, 0u, 0u);
        *(uint4*)&g_Ahi[off] = z;
        *(uint4*)&g_Alo[off] = z;
    }
    if (gt < HID * HID) {
        int k = gt >> 8, n = gt & 255;
        float x = gW[gt];                            // W[k][n], coalesced read
        __nv_bfloat16 h = __float2bfloat16_rn(x);
        __nv_bfloat16 l = __float2bfloat16_rn(x - __bfloat162float(h));
        g_Bhi[n * HID + k] = h;
        g_Blo[n * HID + k] = l;
    }

    // ---- attention projection GEMM ----
    __shared__ float Xs[ABM][ABK + XPAD];   // 18 KB
    __shared__ float Ws[ABK][ATTN];         // 4 KB

    int b = blockIdx.x;
    const float* X;
    const float* Wb;
    float*       out;
    int          nrows, row0, grow0;
    if (b < ublk) {
        X = uemb; Wb = W1;                      out = g_U1;
        nrows = n_users; row0 = b * ABM; grow0 = row0;
    } else {
        X = iemb; Wb = W1 + (size_t)HID * ATTN; out = g_I1;
        nrows = n_items; row0 = (b - ublk) * ABM; grow0 = n_users + row0;
    }

    int tid = threadIdx.x;
    int lxr = tid >> 1;            // 0..127
    int lxc = (tid & 1) * 16;      // 0 or 16
    int lwr = tid >> 3;            // 0..31
    int lwc = (tid & 7) * 4;       // 0..28
    int tr = (tid >> 3) * 4;       // 0..124
    int tc = (tid & 7) * 4;        // 0..28

    float acc[4][4];
    #pragma unroll
    for (int m = 0; m < 4; m++)
        #pragma unroll
        for (int n = 0; n < 4; n++) acc[m][n] = 0.f;

    int xrow = row0 + lxr;
    const float* xp = (xrow < nrows) ? (X + (size_t)xrow * HID) : nullptr;
    size_t aoff0 = (size_t)(grow0 + lxr) * HID + lxc;

    for (int kk = 0; kk < HID; kk += ABK) {
        float4 v0 = make_float4(0.f,0.f,0.f,0.f), v1 = v0, v2 = v0, v3 = v0;
        if (xp) {
            v0 = *(const float4*)(xp + kk + lxc);
            v1 = *(const float4*)(xp + kk + lxc + 4);
            v2 = *(const float4*)(xp + kk + lxc + 8);
            v3 = *(const float4*)(xp + kk + lxc + 12);
        }
        *(float4*)&Xs[lxr][lxc]      = v0;
        *(float4*)&Xs[lxr][lxc + 4]  = v1;
        *(float4*)&Xs[lxr][lxc + 8]  = v2;
        *(float4*)&Xs[lxr][lxc + 12] = v3;

        if (xp) {
            float f[16];
            f[0]=v0.x; f[1]=v0.y; f[2]=v0.z; f[3]=v0.w;
            f[4]=v1.x; f[5]=v1.y; f[6]=v1.z; f[7]=v1.w;
            f[8]=v2.x; f[9]=v2.y; f[10]=v2.z; f[11]=v2.w;
            f[12]=v3.x; f[13]=v3.y; f[14]=v3.z; f[15]=v3.w;
            unsigned hip[8], lop[8];
            #pragma unroll
            for (int i = 0; i < 8; i++) {
                __nv_bfloat162 h = __floats2bfloat162_rn(f[2*i], f[2*i+1]);
                hip[i] = *(unsigned*)&h;
                __nv_bfloat162 l = __floats2bfloat162_rn(
                    f[2*i]   - __bfloat162float(__low2bfloat16(h)),
                    f[2*i+1] - __bfloat162float(__high2bfloat16(h)));
                lop[i] = *(unsigned*)&l;
            }
            size_t off = aoff0 + kk;
            *(uint4*)&g_Ahi[off]     = make_uint4(hip[0], hip[1], hip[2], hip[3]);
            *(uint4*)&g_Ahi[off + 8] = make_uint4(hip[4], hip[5], hip[6], hip[7]);
            *(uint4*)&g_Alo[off]     = make_uint4(lop[0], lop[1], lop[2], lop[3]);
            *(uint4*)&g_Alo[off + 8] = make_uint4(lop[4], lop[5], lop[6], lop[7]);
        }

        *(float4*)&Ws[lwr][lwc] =
            *(const float4*)(Wb + (size_t)(kk + lwr) * ATTN + lwc);
        __syncthreads();

        #pragma unroll
        for (int k4 = 0; k4 < ABK; k4 += 4) {
            float4 xa0 = *(const float4*)&Xs[tr + 0][k4];
            float4 xa1 = *(const float4*)&Xs[tr + 1][k4];
            float4 xa2 = *(const float4*)&Xs[tr + 2][k4];
            float4 xa3 = *(const float4*)&Xs[tr + 3][k4];
            float4 w0  = *(const float4*)&Ws[k4 + 0][tc];
            float4 w1  = *(const float4*)&Ws[k4 + 1][tc];
            float4 w2  = *(const float4*)&Ws[k4 + 2][tc];
            float4 w3  = *(const float4*)&Ws[k4 + 3][tc];
            #pragma unroll
            for (int m = 0; m < 4; m++) {
                float4 xm = (m == 0) ? xa0 : (m == 1) ? xa1 : (m == 2) ? xa2 : xa3;
                acc[m][0] += xm.x * w0.x + xm.y * w1.x + xm.z * w2.x + xm.w * w3.x;
                acc[m][1] += xm.x * w0.y + xm.y * w1.y + xm.z * w2.y + xm.w * w3.y;
                acc[m][2] += xm.x * w0.z + xm.y * w1.z + xm.z * w2.z + xm.w * w3.z;
                acc[m][3] += xm.x * w0.w + xm.y * w1.w + xm.z * w2.w + xm.w * w3.w;
            }
        }
        __syncthreads();
    }

    #pragma unroll
    for (int m = 0; m < 4; m++) {
        int r = row0 + tr + m;
        if (r < nrows)
            *(float4*)(out + (size_t)r * ATTN + tc) =
                make_float4(acc[m][0], acc[m][1], acc[m][2], acc[m][3]);
    }
}

// ---------------- K2: edge weights + fused finalize (common case) ------------
// Writes out_edge and deg atomics inline (keep = w > THR). Count/max
// bookkeeping retained for the all-dropped fallback, handled by K3/K4.
__global__ void edge_weight_kernel(const int* __restrict__ ei,
                                   const float* __restrict__ b1,
                                   const float* __restrict__ W2,
                                   const float* __restrict__ b2,
                                   float* __restrict__ out_edge,
                                   int n_edges) {
    int e = blockIdx.x * blockDim.x + threadIdx.x;
    bool valid = (e < n_edges);
    float w = 0.f;
    if (valid) {
        int s = ei[e];
        int d = ei[n_edges + e];
        const float4* u4 = (const float4*)(g_U1 + (size_t)s * ATTN);
        const float4* i4 = (const float4*)(g_I1 + (size_t)d * ATTN);
        const float4* b4 = (const float4*)b1;
        const float4* w4 = (const float4*)W2;
        float sum = 0.f;
        #pragma unroll
        for (int q = 0; q < ATTN / 4; q++) {
            float4 a = u4[q], b = i4[q], c = b4[q], v = w4[q];
            float h;
            h = a.x + b.x + c.x; h = (h >= 0.f) ? h : 0.2f * h; sum += h * v.x;
            h = a.y + b.y + c.y; h = (h >= 0.f) ? h : 0.2f * h; sum += h * v.y;
            h = a.z + b.z + c.z; h = (h >= 0.f) ? h : 0.2f * h; sum += h * v.z;
            h = a.w + b.w + c.w; h = (h >= 0.f) ? h : 0.2f * h; sum += h * v.w;
        }
        float z = sum + b2[0];
        w = 1.0f / (1.0f + expf(-z));
        g_w[e] = w;
        bool keep = (w > THR);
        out_edge[e] = keep ? w : 0.0f;
        if (keep) atomicAdd(&g_deg[d], 1.0f);
    }
    unsigned keepmask = __ballot_sync(0xffffffffu, valid && (w > THR));
    unsigned bits     = valid ? __float_as_uint(w) : 0u;
    unsigned mx       = __reduce_max_sync(0xffffffffu, bits);
    if ((threadIdx.x & 31) == 0) {
        if (keepmask) atomicAdd(&g_count, __popc(keepmask));
        atomicMax(&g_maxbits, mx);
    }
}

// ---------------- K3: fallback argmax (no-op when any edge kept) -------------
__global__ void argmax_kernel(int n_edges) {
    if (g_count > 0) return;
    int stride = gridDim.x * blockDim.x;
    for (int e = blockIdx.x * blockDim.x + threadIdx.x; e < n_edges; e += stride)
        if (__float_as_uint(g_w[e]) == g_maxbits) atomicMin(&g_argidx, e);
}

// ---------------- K4: fallback apply (no-op when any edge kept) --------------
__global__ void fixup_kernel(const int* __restrict__ ei,
                             float* __restrict__ out_edge, int n_edges) {
    if (g_count > 0) return;
    if (blockIdx.x == 0 && threadIdx.x == 0) {
        int e = g_argidx;
        float w = g_w[e];
        out_edge[e] = w;
        atomicAdd(&g_deg[ei[n_edges + e]], 1.0f);
    }
}

// ---------------- K5: split-bf16 HMMA GEMM (double-buffered 3-pass) ----------
// C = Ahi*Bhi + Ahi*Blo + Alo*Bhi   (3 passes over K=256, bf16, fp32 accum)
#define GBM 128
#define GBN 128
#define GBK 32
#define BKP 40            // padded smem k-stride (bf16): conflict-free frags

__global__ __launch_bounds__(256, 2)
void gemm_bf16_kernel(const float* __restrict__ bias,
                      float* __restrict__ out_gcn, int n_nodes) {
    __shared__ __nv_bfloat16 As[2][GBM * BKP];
    __shared__ __nv_bfloat16 Bs[2][GBN * BKP];

    const int tid  = threadIdx.x;
    const int warp = tid >> 5;
    const int lane = tid & 31;
    const int wr   = warp >> 2;          // 0..1
    const int wc   = warp & 3;           // 0..3
    const int grp  = lane >> 2;          // 0..7
    const int tq   = lane & 3;           // 0..3
    const int row0 = blockIdx.x * GBM;
    const int col0 = blockIdx.y * GBN;

    const int lr = tid >> 2;             // 0..63
    const int lc = (tid & 3) * 8;        // 0,8,16,24

    float acc[4][4][4];
    #pragma unroll
    for (int mf = 0; mf < 4; mf++)
        #pragma unroll
        for (int nf = 0; nf < 4; nf++)
            #pragma unroll
            for (int c = 0; c < 4; c++) acc[mf][nf][c] = 0.f;

    const int NT = 3 * (HID / GBK);      // 24 tiles

    uint4 ra0, ra1, rb0, rb1;
    auto ldg_tile = [&](int t, uint4& a0, uint4& a1, uint4& b0, uint4& b1) {
        int pass = t >> 3;
        int kk   = (t & 7) * GBK;
        const __nv_bfloat16* Ap = (pass == 2) ? g_Alo : g_Ahi;
        const __nv_bfloat16* Bp = (pass == 1) ? g_Blo : g_Bhi;
        a0 = *(const uint4*)(Ap + (size_t)(row0 + lr)      * HID + kk + lc);
        a1 = *(const uint4*)(Ap + (size_t)(row0 + lr + 64) * HID + kk + lc);
        b0 = *(const uint4*)(Bp + (size_t)(col0 + lr)      * HID + kk + lc);
        b1 = *(const uint4*)(Bp + (size_t)(col0 + lr + 64) * HID + kk + lc);
    };
    auto sts_tile = [&](int buf, uint4 a0, uint4 a1, uint4 b0, uint4 b1) {
        uint2* pa0 = (uint2*)&As[buf][lr * BKP + lc];
        pa0[0] = make_uint2(a0.x, a0.y); pa0[1] = make_uint2(a0.z, a0.w);
        uint2* pa1 = (uint2*)&As[buf][(lr + 64) * BKP + lc];
        pa1[0] = make_uint2(a1.x, a1.y); pa1[1] = make_uint2(a1.z, a1.w);
        uint2* pb0 = (uint2*)&Bs[buf][lr * BKP + lc];
        pb0[0] = make_uint2(b0.x, b0.y); pb0[1] = make_uint2(b0.z, b0.w);
        uint2* pb1 = (uint2*)&Bs[buf][(lr + 64) * BKP + lc];
        pb1[0] = make_uint2(b1.x, b1.y); pb1[1] = make_uint2(b1.z, b1.w);
    };

    ldg_tile(0, ra0, ra1, rb0, rb1);
    sts_tile(0, ra0, ra1, rb0, rb1);
    __syncthreads();

    int cur = 0;
    for (int t = 0; t < NT; t++) {
        bool has_next = (t + 1 < NT);
        if (has_next) ldg_tile(t + 1, ra0, ra1, rb0, rb1);

        #pragma unroll
        for (int ks = 0; ks < 2; ks++) {
            int k0 = ks * 16;
            unsigned afr[4][4], bfr[4][2];
            #pragma unroll
            for (int mf = 0; mf < 4; mf++) {
                const __nv_bfloat16* ab =
                    &As[cur][(wr * 64 + mf * 16 + grp) * BKP + k0 + 2 * tq];
                afr[mf][0] = *(const unsigned*)(ab);
                afr[mf][1] = *(const unsigned*)(ab + 8 * BKP);
                afr[mf][2] = *(const unsigned*)(ab + 8);
                afr[mf][3] = *(const unsigned*)(ab + 8 * BKP + 8);
            }
            #pragma unroll
            for (int nf = 0; nf < 4; nf++) {
                const __nv_bfloat16* bb =
                    &Bs[cur][(wc * 32 + nf * 8 + grp) * BKP + k0 + 2 * tq];
                bfr[nf][0] = *(const unsigned*)(bb);
                bfr[nf][1] = *(const unsigned*)(bb + 8);
            }
            #pragma unroll
            for (int mf = 0; mf < 4; mf++)
                #pragma unroll
                for (int nf = 0; nf < 4; nf++) {
                    float* c = acc[mf][nf];
                    asm volatile(
                        "mma.sync.aligned.m16n8k16.row.col.f32.bf16.bf16.f32 "
                        "{%0,%1,%2,%3}, {%4,%5,%6,%7}, {%8,%9}, {%0,%1,%2,%3};"
                        : "+f"(c[0]), "+f"(c[1]), "+f"(c[2]), "+f"(c[3])
                        : "r"(afr[mf][0]), "r"(afr[mf][1]),
                          "r"(afr[mf][2]), "r"(afr[mf][3]),
                          "r"(bfr[nf][0]), "r"(bfr[nf][1]));
                }
        }

        if (has_next) {
            int nxt = cur ^ 1;
            sts_tile(nxt, ra0, ra1, rb0, rb1);
            __syncthreads();
            cur = nxt;
        }
    }

    #pragma unroll
    for (int mf = 0; mf < 4; mf++) {
        int r1 = row0 + wr * 64 + mf * 16 + grp;
        int r2 = r1 + 8;
        float s1 = (r1 < n_nodes) ? (1.0f / g_deg[r1]) : 0.f;
        float s2 = (r2 < n_nodes) ? (1.0f / g_deg[r2]) : 0.f;
        #pragma unroll
        for (int nf = 0; nf < 4; nf++) {
            int cc = col0 + wc * 32 + nf * 8 + 2 * tq;
            float2 b = *(const float2*)(bias + cc);
            const float* c = acc[mf][nf];
            if (r1 < n_nodes) {
                *(float2*)(g_xw    + (size_t)r1 * HID + cc) = make_float2(c[0], c[1]);
                *(float2*)(out_gcn + (size_t)r1 * HID + cc) =
                    make_float2(c[0] * s1 + b.x, c[1] * s1 + b.y);
            }
            if (r2 < n_nodes) {
                *(float2*)(g_xw    + (size_t)r2 * HID + cc) = make_float2(c[2], c[3]);
                *(float2*)(out_gcn + (size_t)r2 * HID + cc) =
                    make_float2(c[2] * s2 + b.x, c[3] * s2 + b.y);
            }
        }
    }
}

// ---------------- K6: ballot-scan scatter (no compaction buffer) -------------
__global__ void scatter_kernel(const int* __restrict__ ei,
                               const float* __restrict__ out_edge,
                               float* __restrict__ out_gcn, int n_edges) {
    int gw     = (blockIdx.x * blockDim.x + threadIdx.x) >> 5;
    int lane   = threadIdx.x & 31;
    int nw     = (gridDim.x * blockDim.x) >> 5;
    int nchunk = (n_edges + 31) >> 5;

    for (int chunk = gw; chunk < nchunk; chunk += nw) {
        int e0 = chunk << 5;
        int e  = e0 + lane;
        float w = (e < n_edges) ? out_edge[e] : 0.f;
        unsigned m = __ballot_sync(0xffffffffu, w != 0.f);
        while (m) {
            int b = __ffs(m) - 1;
            m &= m - 1;
            int ee = e0 + b;
            int s = ei[ee];
            int d = ei[n_edges + ee];
            float coef = rsqrtf(g_deg[s]) * rsqrtf(g_deg[d]);
            const float4* xr   = (const float4*)(g_xw + (size_t)s * HID);
            float4*       orow = (float4*)(out_gcn + (size_t)d * HID);
            #pragma unroll
            for (int j = 0; j < HID / 128; j++) {
                float4 v = xr[lane + 32 * j];
                v.x *= coef; v.y *= coef; v.z *= coef; v.w *= coef;
                asm volatile("red.global.add.v4.f32 [%0], {%1, %2, %3, %4};"
                             :: "l"(&orow[lane + 32 * j]),
                                "f"(v.x), "f"(v.y), "f"(v.z), "f"(v.w)
                             : "memory");
            }
        }
    }
}

// ---------------- launch ------------------------------------------------------
extern "C" void kernel_launch(void* const* d_in, const int* in_sizes, int n_in,
                              void* d_out, int out_size) {
    const float* uemb = (const float*)d_in[0];
    const float* iemb = (const float*)d_in[1];
    const int*   ei   = (const int*)d_in[2];
    const float* W1   = (const float*)d_in[3];
    const float* b1   = (const float*)d_in[4];
    const float* W2   = (const float*)d_in[5];
    const float* b2   = (const float*)d_in[6];
    const float* gW   = (const float*)d_in[7];
    const float* gb   = (const float*)d_in[8];

    int n_users = in_sizes[0] / HID;
    int n_items = in_sizes[1] / HID;
    int n_edges = in_sizes[2] / 2;
    int n_nodes = n_users + n_items;

    float* out_gcn  = (float*)d_out;
    float* out_edge = out_gcn + (size_t)n_nodes * HID;

    int ublk = (n_users + ABM - 1) / ABM;
    int iblk = (n_items + ABM - 1) / ABM;
    attn_precompute_kernel<<<ublk + iblk, 256>>>(uemb, iemb, W1, gW,
                                                 n_users, n_items, n_nodes, ublk);

    edge_weight_kernel<<<(n_edges + 255) / 256, 256>>>(ei, b1, W2, b2,
                                                       out_edge, n_edges);

    argmax_kernel<<<592, 256>>>(n_edges);

    fixup_kernel<<<1, 32>>>(ei, out_edge, n_edges);

    dim3 ggrid(MPAD / GBM, HID / GBN);
    gemm_bf16_kernel<<<ggrid, 256>>>(gb, out_gcn, n_nodes);

    scatter_kernel<<<1184, 256>>>(ei, out_edge, out_gcn, n_edges);
}